// round 1
// baseline (speedup 1.0000x reference)
#include <cuda_runtime.h>
#include <math.h>

#define NN 100000
#define NE 1600000

// ---------------- scratch (device globals: allocation-free) ----------------
__device__ __align__(16) float g_xin[NN * 64];
__device__ __align__(16) float g_outf[NN * 64];
__device__ __align__(16) float g_outb[NN * 64];
__device__ float g_degf[NN];
__device__ float g_degb[NN];

// ---------------- zero scratch ----------------
__global__ void k_zero() {
    int i = blockIdx.x * blockDim.x + threadIdx.x;
    int stride = gridDim.x * blockDim.x;
    float4 z = make_float4(0.f, 0.f, 0.f, 0.f);
    for (int j = i; j < NN * 16; j += stride) {   // NN*64/4
        reinterpret_cast<float4*>(g_outf)[j] = z;
        reinterpret_cast<float4*>(g_outb)[j] = z;
    }
    for (int j = i; j < NN; j += stride) { g_degf[j] = 0.f; g_degb[j] = 0.f; }
}

// ---------------- weighted degrees ----------------
__global__ void k_deg(const int* __restrict__ ei, const float* __restrict__ ew) {
    int e = blockIdx.x * blockDim.x + threadIdx.x;
    if (e >= NE) return;
    int s = ei[e], t = ei[NE + e];
    float w = ew[e];
    if (s != t) {
        atomicAdd(&g_degf[t], w);
        atomicAdd(&g_degb[s], w);
    }
}

// ---------------- x_in = concat(x, x_hat_1, h) @ W_in + b_in ----------------
// W transposed into SMEM: Wt[col][k], k padded 161 -> 164 (float4 + bank spread).
// Block = 256 threads: col = tid&63, grp = tid>>6 handles 8 nodes.
// 32 nodes per block, 3125 blocks exactly cover N.
#define XTP 164
#define XIN_SMEM (((64 + 32) * XTP + 64) * 4)

__global__ __launch_bounds__(256) void k_xin(const float* __restrict__ x,
                                             const float* __restrict__ xh,
                                             const float* __restrict__ hh,
                                             const float* __restrict__ Win,
                                             const float* __restrict__ bin) {
    extern __shared__ float sm[];
    float* Wt   = sm;                 // [64][XTP]
    float* rows = Wt + 64 * XTP;      // [32][XTP]
    float* bs   = rows + 32 * XTP;    // [64]

    for (int i = threadIdx.x; i < 64 * XTP; i += 256) Wt[i] = 0.f;
    __syncthreads();
    for (int i = threadIdx.x; i < 161 * 64; i += 256) {
        int k = i >> 6, c = i & 63;
        Wt[c * XTP + k] = Win[i];
    }
    if (threadIdx.x < 64) bs[threadIdx.x] = bin[threadIdx.x];

    const int col = threadIdx.x & 63;
    const int grp = threadIdx.x >> 6;          // 0..3
    const int base = blockIdx.x * 32;

    // cooperative load of 32 input rows (zero-padded to XTP)
    __syncthreads();
    for (int i = threadIdx.x; i < 32 * XTP; i += 256) {
        int s = i / XTP, k = i - s * XTP;
        int n = base + s;
        float v = 0.f;
        if (k < 161) {
            v = (k == 0) ? x[n]
              : (k < 97) ? xh[(size_t)n * 96 + (k - 1)]
                         : hh[(size_t)n * 64 + (k - 97)];
        }
        rows[i] = v;
    }
    __syncthreads();

    float acc[8];
#pragma unroll
    for (int s = 0; s < 8; s++) acc[s] = 0.f;

    const float4* wp = reinterpret_cast<const float4*>(Wt + col * XTP);
    const float4* rp = reinterpret_cast<const float4*>(rows + grp * 8 * XTP);
#pragma unroll
    for (int k4 = 0; k4 < XTP / 4; k4++) {
        float4 w = wp[k4];
#pragma unroll
        for (int s = 0; s < 8; s++) {
            float4 v = rp[s * (XTP / 4) + k4];
            acc[s] += w.x * v.x + w.y * v.y + w.z * v.z + w.w * v.w;
        }
    }
    float b = bs[col];
#pragma unroll
    for (int s = 0; s < 8; s++) {
        int n = base + grp * 8 + s;
        g_xin[(size_t)n * 64 + col] = acc[s] + b;
    }
}

// ---------------- edge scatter (forward + backward diffusion) ----------------
__device__ __forceinline__ void red2(float* p, float a, float b) {
    asm volatile("red.global.add.v2.f32 [%0], {%1, %2};"
                 :: "l"(p), "f"(a), "f"(b) : "memory");
}

__global__ __launch_bounds__(256) void k_scatter(const int* __restrict__ ei,
                                                 const float* __restrict__ ew) {
    unsigned tid = blockIdx.x * 256u + threadIdx.x;
    unsigned e = tid >> 5;           // one warp per edge
    if (e >= NE) return;
    int lane = threadIdx.x & 31;

    int s = __ldg(&ei[e]);
    int t = __ldg(&ei[NE + e]);
    float w = __ldg(&ew[e]);
    if (s == t) w = 0.f;
    float df = g_degf[t];
    float db = g_degb[s];
    float wf = (df > 0.f) ? w / df : 0.f;
    float wb = (db > 0.f) ? w / db : 0.f;

    const float2 xs = *reinterpret_cast<const float2*>(g_xin + (size_t)s * 64 + 2 * lane);
    red2(g_outf + (size_t)t * 64 + 2 * lane, wf * xs.x, wf * xs.y);
    const float2 xt = *reinterpret_cast<const float2*>(g_xin + (size_t)t * 64 + 2 * lane);
    red2(g_outb + (size_t)s * 64 + 2 * lane, wb * xt.x, wb * xt.y);
}

// ---------------- fused filter GEMV + GMM heads + outputs ----------------
// Block = 256 (8 warps). Each warp handles 4 nodes. Weights transposed+padded
// (128 -> JP=132) in dynamic SMEM; per-warp cat buffer holds [outf|outb] then
// is rebuilt in place as out1 = [out|h].
#define JP 132
#define HEAD_SMEM ((64 * JP + 3 * 32 * JP + 160 + 8 * 4 * 128) * 4)

__global__ __launch_bounds__(256) void k_head(const float* __restrict__ hh,
                                              const float* __restrict__ Wf,  const float* __restrict__ bf,
                                              const float* __restrict__ Wm,  const float* __restrict__ bm,
                                              const float* __restrict__ Wsg, const float* __restrict__ bsg,
                                              const float* __restrict__ Wp,  const float* __restrict__ bp,
                                              float* __restrict__ out, int write_extra) {
    extern __shared__ float sm[];
    float* Wft = sm;                    // [64][JP]
    float* Wmt = Wft + 64 * JP;         // [32][JP]
    float* Wst = Wmt + 32 * JP;
    float* Wpt = Wst + 32 * JP;
    float* bfs = Wpt + 32 * JP;         // 64
    float* bms = bfs + 64;              // 32
    float* bss = bms + 32;              // 32
    float* bps = bss + 32;              // 32
    float* cat = bps + 32;              // [8 warps][4 nodes][128]

    for (int i = threadIdx.x; i < 64 * JP; i += 256) Wft[i] = 0.f;
    for (int i = threadIdx.x; i < 32 * JP; i += 256) { Wmt[i] = 0.f; Wst[i] = 0.f; Wpt[i] = 0.f; }
    __syncthreads();
    for (int i = threadIdx.x; i < 128 * 64; i += 256) {
        int j = i >> 6, c = i & 63;
        Wft[c * JP + j] = Wf[i];
    }
    for (int i = threadIdx.x; i < 128 * 32; i += 256) {
        int j = i >> 5, c = i & 31;
        Wmt[c * JP + j] = Wm[i];
        Wst[c * JP + j] = Wsg[i];
        Wpt[c * JP + j] = Wp[i];
    }
    if (threadIdx.x < 64) bfs[threadIdx.x] = bf[threadIdx.x];
    if (threadIdx.x < 32) {
        bms[threadIdx.x] = bm[threadIdx.x];
        bss[threadIdx.x] = bsg[threadIdx.x];
        bps[threadIdx.x] = bp[threadIdx.x];
    }
    __syncthreads();

    const int lane = threadIdx.x & 31;
    const int wrp  = threadIdx.x >> 5;
    float* mycat = cat + wrp * 4 * 128;

    float* ogmm = out;
    float* oo1  = out + (size_t)NN * 96;
    float* oh   = out + (size_t)NN * 96 + (size_t)NN * 128;

    int base = blockIdx.x * 32 + wrp * 4;          // 3125 blocks * 32 = NN exactly
    if (base >= NN) return;

    // 1) load cat = [outf(64) | outb(64)] for 4 nodes
#pragma unroll
    for (int s = 0; s < 4; s++) {
        size_t n = (size_t)(base + s);
        float* c = mycat + s * 128;
        c[lane]      = g_outf[n * 64 + lane];
        c[lane + 32] = g_outf[n * 64 + 32 + lane];
        c[lane + 64] = g_outb[n * 64 + lane];
        c[lane + 96] = g_outb[n * 64 + 32 + lane];
    }
    __syncwarp();

    // 2) out = cat @ W_filt : lane computes cols lane and lane+32
    float a0[4] = {0.f, 0.f, 0.f, 0.f};
    float a1[4] = {0.f, 0.f, 0.f, 0.f};
    {
        const float4* w0p = reinterpret_cast<const float4*>(Wft + lane * JP);
        const float4* w1p = reinterpret_cast<const float4*>(Wft + (lane + 32) * JP);
#pragma unroll 8
        for (int j4 = 0; j4 < 32; j4++) {
            float4 w0 = w0p[j4], w1 = w1p[j4];
#pragma unroll
            for (int s = 0; s < 4; s++) {
                float4 v = reinterpret_cast<const float4*>(mycat + s * 128)[j4];
                a0[s] += w0.x * v.x + w0.y * v.y + w0.z * v.z + w0.w * v.w;
                a1[s] += w1.x * v.x + w1.y * v.y + w1.z * v.z + w1.w * v.w;
            }
        }
    }
    __syncwarp();

    // 3) rebuild cat in place as out1 = [out(64) | h(64)]
    float h0[4], h1[4];
#pragma unroll
    for (int s = 0; s < 4; s++) {
        size_t n = (size_t)(base + s);
        a0[s] += bfs[lane];
        a1[s] += bfs[lane + 32];
        h0[s] = hh[n * 64 + lane];
        h1[s] = hh[n * 64 + 32 + lane];
        float* c = mycat + s * 128;
        c[lane]      = a0[s];
        c[lane + 32] = a1[s];
        c[lane + 64] = h0[s];
        c[lane + 96] = h1[s];
    }
    __syncwarp();

    // 4) heads: lane computes mu[lane], sigma[lane], pi[lane]
    float am[4] = {0.f, 0.f, 0.f, 0.f};
    float as_[4] = {0.f, 0.f, 0.f, 0.f};
    float ap[4] = {0.f, 0.f, 0.f, 0.f};
    {
        const float4* wmp = reinterpret_cast<const float4*>(Wmt + lane * JP);
        const float4* wsp = reinterpret_cast<const float4*>(Wst + lane * JP);
        const float4* wpp = reinterpret_cast<const float4*>(Wpt + lane * JP);
#pragma unroll 8
        for (int j4 = 0; j4 < 32; j4++) {
            float4 wm = wmp[j4], ws = wsp[j4], wq = wpp[j4];
#pragma unroll
            for (int s = 0; s < 4; s++) {
                float4 v = reinterpret_cast<const float4*>(mycat + s * 128)[j4];
                am[s]  += wm.x * v.x + wm.y * v.y + wm.z * v.z + wm.w * v.w;
                as_[s] += ws.x * v.x + ws.y * v.y + ws.z * v.z + ws.w * v.w;
                ap[s]  += wq.x * v.x + wq.y * v.y + wq.z * v.z + wq.w * v.w;
            }
        }
    }

    // 5) epilogue per node: softplus / softmax + all output writes
#pragma unroll
    for (int s = 0; s < 4; s++) {
        size_t n = (size_t)(base + s);
        float mu = am[s] + bms[lane];
        float sg = as_[s] + bss[lane];
        sg = fmaxf(sg, 0.f) + log1pf(__expf(-fabsf(sg)));   // stable softplus
        float pv = ap[s] + bps[lane];
        float m = pv;
#pragma unroll
        for (int o = 16; o; o >>= 1) m = fmaxf(m, __shfl_xor_sync(0xFFFFFFFFu, m, o));
        float ex = __expf(pv - m);
        float ssum = ex;
#pragma unroll
        for (int o = 16; o; o >>= 1) ssum += __shfl_xor_sync(0xFFFFFFFFu, ssum, o);
        float pi = ex / ssum;

        ogmm[n * 96 + lane]      = mu;
        ogmm[n * 96 + 32 + lane] = sg;
        ogmm[n * 96 + 64 + lane] = pi;
        if (write_extra) {
            oo1[n * 128 + lane]      = a0[s];
            oo1[n * 128 + 32 + lane] = a1[s];
            oo1[n * 128 + 64 + lane] = h0[s];
            oo1[n * 128 + 96 + lane] = h1[s];
            oh[n * 64 + lane]      = h0[s];
            oh[n * 64 + 32 + lane] = h1[s];
        }
    }
}

// ---------------- launch ----------------
extern "C" void kernel_launch(void* const* d_in, const int* in_sizes, int n_in,
                              void* d_out, int out_size) {
    const float* x   = (const float*)d_in[0];
    const float* xh  = (const float*)d_in[1];
    const float* h   = (const float*)d_in[2];
    const int*   ei  = (const int*)d_in[3];
    const float* ew  = (const float*)d_in[4];
    const float* Win = (const float*)d_in[5];
    const float* bin = (const float*)d_in[6];
    const float* Wf  = (const float*)d_in[7];
    const float* bf  = (const float*)d_in[8];
    const float* Wm  = (const float*)d_in[9];
    const float* bm  = (const float*)d_in[10];
    const float* Wsg = (const float*)d_in[11];
    const float* bsg = (const float*)d_in[12];
    const float* Wp  = (const float*)d_in[13];
    const float* bp  = (const float*)d_in[14];
    float* out = (float*)d_out;

    // full tuple output = N*(96+128+64); fall back to gmm-only if smaller
    int write_extra = (out_size >= NN * 96 + NN * 128 + NN * 64) ? 1 : 0;

    cudaFuncSetAttribute(k_xin,  cudaFuncAttributeMaxDynamicSharedMemorySize, XIN_SMEM);
    cudaFuncSetAttribute(k_head, cudaFuncAttributeMaxDynamicSharedMemorySize, HEAD_SMEM);

    k_zero<<<512, 256>>>();
    k_deg<<<(NE + 255) / 256, 256>>>(ei, ew);
    k_xin<<<3125, 256, XIN_SMEM>>>(x, xh, h, Win, bin);
    k_scatter<<<(NE * 32 + 255) / 256, 256>>>(ei, ew);
    k_head<<<3125, 256, HEAD_SMEM>>>(h, Wf, bf, Wm, bm, Wsg, bsg, Wp, bp, out, write_extra);
}